// round 14
// baseline (speedup 1.0000x reference)
#include <cuda_runtime.h>
#include <cuda_fp16.h>

// Problem constants
#define CUBE_L   512
#define EQU_H    1024
#define EQU_W    2048
#define N_EQU    4
#define N_CH     3
#define N_PIX    (EQU_H * EQU_W)        // 2,097,152
#define LL       (CUBE_L * CUBE_L)      // 262,144
#define N_PLANES (N_CH * 6)             // 18 packed planes (c,f)
#define IMG_STRIDE (6 * N_CH * LL)      // elements between equirect images in x

// Persistent-grid sizing (single wave, exact division)
#define RP_BLOCKS  768
#define RP_ITERS   6      // 768*6*256*4 texels = 18*LL
#define GA_BLOCKS  1024
#define GA_ITERS   8      // 1024*8 tiles = 64*128 tiles

// Scratch: x repacked as x̃[(c*6+f)][y*L+x] = uint2 holding fp16 values for
// e = 0..3 (half2(e0,e1), half2(e2,e3)). 18 * 262144 * 8B = 37.75 MB.
__device__ uint2 g_xt[N_PLANES * LL];

static __device__ __forceinline__ unsigned int h2_as_u32(__half2 h) {
    return *reinterpret_cast<unsigned int*>(&h);
}
static __device__ __forceinline__ __half2 u32_as_h2(unsigned int u) {
    return *reinterpret_cast<__half2*>(&u);
}

// ---------------- Pass 1: repack (4 texels/thread, persistent 1-wave grid) --
__global__ __launch_bounds__(256, 6)
void repack_kernel(const float* __restrict__ x)
{
    #pragma unroll
    for (int k = 0; k < RP_ITERS; k++) {
        int vb = blockIdx.x + k * RP_BLOCKS;
        int T = vb * 256 + threadIdx.x;      // 0 .. 18*LL/4 - 1
        int plane = T >> 16;                 // / (LL/4)
        int i     = (T & 0xFFFF) << 2;       // 4 consecutive texels
        int c = plane / 6;
        int f = plane % 6;

        int base = f * (N_CH * LL) + c * LL + i;
        // Streaming reads: x is never re-read; keep it out of L2 so the
        // packed intermediate stays resident for the gather pass.
        float4 a0 = __ldcs(reinterpret_cast<const float4*>(x + base));
        float4 a1 = __ldcs(reinterpret_cast<const float4*>(x + base + 1 * IMG_STRIDE));
        float4 a2 = __ldcs(reinterpret_cast<const float4*>(x + base + 2 * IMG_STRIDE));
        float4 a3 = __ldcs(reinterpret_cast<const float4*>(x + base + 3 * IMG_STRIDE));

        uint4 v01, v23;   // two texels each: (x,y)=texel j, (z,w)=texel j+1
        v01.x = h2_as_u32(__floats2half2_rn(a0.x, a1.x));
        v01.y = h2_as_u32(__floats2half2_rn(a2.x, a3.x));
        v01.z = h2_as_u32(__floats2half2_rn(a0.y, a1.y));
        v01.w = h2_as_u32(__floats2half2_rn(a2.y, a3.y));
        v23.x = h2_as_u32(__floats2half2_rn(a0.z, a1.z));
        v23.y = h2_as_u32(__floats2half2_rn(a2.z, a3.z));
        v23.z = h2_as_u32(__floats2half2_rn(a0.w, a1.w));
        v23.w = h2_as_u32(__floats2half2_rn(a2.w, a3.w));

        uint4* dst = reinterpret_cast<uint4*>(g_xt + plane * LL + i);
        dst[0] = v01;
        dst[1] = v23;
    }

    // Writes above are visible to the dependent grid after its
    // cudaGridDependencySynchronize (trigger is after all stores).
    cudaTriggerProgrammaticLaunchCompletion();
}

// ---------------- Pass 2: gather + bilinear (persistent 1-wave grid) --------
__global__ __launch_bounds__(256)
void cube2equirec_kernel(const float2* __restrict__ uv,
                         const int* __restrict__ face,
                         float* __restrict__ out)
{
    // Wait once for repack's writes to be visible.
    cudaGridDependencySynchronize();

    const int tx = threadIdx.x & 31;
    const int ty = threadIdx.x >> 5;

    #pragma unroll
    for (int k = 0; k < GA_ITERS; k++) {
        int vt = blockIdx.x + k * GA_BLOCKS;   // virtual tile id, 0..8191
        int px = (vt & 63) * 32 + tx;
        int py = (vt >> 6) * 8 + ty;
        int p  = py * EQU_W + px;

        const float2 t = uv[p];
        const float u = t.x, v = t.y;
        const int f = face[p];

        int x0 = (int)floorf(u);
        int y0 = (int)floorf(v);
        x0 = min(max(x0, 0), CUBE_L - 1);
        y0 = min(max(y0, 0), CUBE_L - 1);
        const int x1 = min(x0 + 1, CUBE_L - 1);
        const int y1 = min(y0 + 1, CUBE_L - 1);
        const float wx = u - (float)x0;
        const float wy = v - (float)y0;

        const float w00 = (1.0f - wx) * (1.0f - wy);
        const float w01 = wx * (1.0f - wy);
        const float w10 = (1.0f - wx) * wy;
        const float w11 = wx * wy;

        const int o00 = y0 * CUBE_L + x0;
        const int o01 = y0 * CUBE_L + x1;
        const int o10 = y1 * CUBE_L + x0;
        const int o11 = y1 * CUBE_L + x1;

        // Issue all 12 gathers up front (MLP).
        uint2 g[N_CH][4];
        #pragma unroll
        for (int c = 0; c < N_CH; c++) {
            const uint2* b = g_xt + (c * 6 + f) * LL;
            g[c][0] = __ldg(b + o00);
            g[c][1] = __ldg(b + o01);
            g[c][2] = __ldg(b + o10);
            g[c][3] = __ldg(b + o11);
        }

        const float w[4] = {w00, w01, w10, w11};

        #pragma unroll
        for (int c = 0; c < N_CH; c++) {
            float r01x = 0.f, r01y = 0.f, r23x = 0.f, r23y = 0.f;
            #pragma unroll
            for (int tap = 0; tap < 4; tap++) {
                float2 a01 = __half22float2(u32_as_h2(g[c][tap].x)); // e0,e1
                float2 a23 = __half22float2(u32_as_h2(g[c][tap].y)); // e2,e3
                r01x += w[tap] * a01.x;
                r01y += w[tap] * a01.y;
                r23x += w[tap] * a23.x;
                r23y += w[tap] * a23.y;
            }
            __stcs(out + (size_t)(0 * N_CH + c) * N_PIX + p, r01x);
            __stcs(out + (size_t)(1 * N_CH + c) * N_PIX + p, r01y);
            __stcs(out + (size_t)(2 * N_CH + c) * N_PIX + p, r23x);
            __stcs(out + (size_t)(3 * N_CH + c) * N_PIX + p, r23y);
        }
    }
}

extern "C" void kernel_launch(void* const* d_in, const int* in_sizes, int n_in,
                              void* d_out, int out_size)
{
    const float*  x    = (const float*)d_in[0];
    const float2* uv   = (const float2*)d_in[1];
    const int*    face = (const int*)d_in[2];
    float*        out  = (float*)d_out;

    // Pass 1: repack — persistent single-wave grid, exact division.
    repack_kernel<<<RP_BLOCKS, 256>>>(x);

    // Pass 2: gather — persistent single-wave grid, PDL-chained.
    cudaLaunchConfig_t cfg = {};
    cfg.gridDim  = dim3(GA_BLOCKS);
    cfg.blockDim = dim3(256);
    cfg.dynamicSmemBytes = 0;
    cfg.stream = 0;
    cudaLaunchAttribute attrs[1];
    attrs[0].id = cudaLaunchAttributeProgrammaticStreamSerialization;
    attrs[0].val.programmaticStreamSerializationAllowed = 1;
    cfg.attrs = attrs;
    cfg.numAttrs = 1;
    cudaLaunchKernelEx(&cfg, cube2equirec_kernel, uv, face, out);
}

// round 16
// speedup vs baseline: 1.0819x; 1.0819x over previous
#include <cuda_runtime.h>
#include <cuda_fp16.h>

// Problem constants
#define CUBE_L   512
#define EQU_H    1024
#define EQU_W    2048
#define N_EQU    4
#define N_CH     3
#define N_PIX    (EQU_H * EQU_W)        // 2,097,152
#define LL       (CUBE_L * CUBE_L)      // 262,144
#define N_PLANES (N_CH * 6)             // 18 packed planes (c,f)
#define IMG_STRIDE (6 * N_CH * LL)      // elements between equirect images in x

// Repack persistent-grid sizing (single wave, exact division)
#define RP_BLOCKS  768
#define RP_ITERS   6      // 768*6*256*4 texels = 18*LL

// Scratch: x repacked as x̃[(c*6+f)][y*L+x] = uint2 holding fp16 values for
// e = 0..3 (half2(e0,e1), half2(e2,e3)). 18 * 262144 * 8B = 37.75 MB.
__device__ uint2 g_xt[N_PLANES * LL];

static __device__ __forceinline__ unsigned int h2_as_u32(__half2 h) {
    return *reinterpret_cast<unsigned int*>(&h);
}
static __device__ __forceinline__ __half2 u32_as_h2(unsigned int u) {
    return *reinterpret_cast<__half2*>(&u);
}

// ---------------- Pass 1: repack (R14 config: persistent, __ldcs) -----------
__global__ __launch_bounds__(256, 6)
void repack_kernel(const float* __restrict__ x)
{
    #pragma unroll
    for (int k = 0; k < RP_ITERS; k++) {
        int vb = blockIdx.x + k * RP_BLOCKS;
        int T = vb * 256 + threadIdx.x;      // 0 .. 18*LL/4 - 1
        int plane = T >> 16;                 // / (LL/4)
        int i     = (T & 0xFFFF) << 2;       // 4 consecutive texels
        int c = plane / 6;
        int f = plane % 6;

        int base = f * (N_CH * LL) + c * LL + i;
        // Streaming reads: x is never re-read; keep it out of L2 so the
        // packed intermediate stays resident for the gather pass.
        float4 a0 = __ldcs(reinterpret_cast<const float4*>(x + base));
        float4 a1 = __ldcs(reinterpret_cast<const float4*>(x + base + 1 * IMG_STRIDE));
        float4 a2 = __ldcs(reinterpret_cast<const float4*>(x + base + 2 * IMG_STRIDE));
        float4 a3 = __ldcs(reinterpret_cast<const float4*>(x + base + 3 * IMG_STRIDE));

        uint4 v01, v23;   // two texels each: (x,y)=texel j, (z,w)=texel j+1
        v01.x = h2_as_u32(__floats2half2_rn(a0.x, a1.x));
        v01.y = h2_as_u32(__floats2half2_rn(a2.x, a3.x));
        v01.z = h2_as_u32(__floats2half2_rn(a0.y, a1.y));
        v01.w = h2_as_u32(__floats2half2_rn(a2.y, a3.y));
        v23.x = h2_as_u32(__floats2half2_rn(a0.z, a1.z));
        v23.y = h2_as_u32(__floats2half2_rn(a2.z, a3.z));
        v23.z = h2_as_u32(__floats2half2_rn(a0.w, a1.w));
        v23.w = h2_as_u32(__floats2half2_rn(a2.w, a3.w));

        uint4* dst = reinterpret_cast<uint4*>(g_xt + plane * LL + i);
        dst[0] = v01;
        dst[1] = v23;
    }

    cudaTriggerProgrammaticLaunchCompletion();
}

// ---------------- Pass 2: gather + bilinear (R13 config: plain grid, PDL) ---
__global__ __launch_bounds__(256)
void cube2equirec_kernel(const float2* __restrict__ uv,
                         const int* __restrict__ face,
                         float* __restrict__ out)
{
    const int px = blockIdx.x * 32 + threadIdx.x;
    const int py = blockIdx.y * 8  + threadIdx.y;
    const int p  = py * EQU_W + px;

    // ---- Preamble (independent of g_xt): runs before repack finishes ----
    const float2 t = uv[p];
    const float u = t.x, v = t.y;
    const int f = face[p];

    int x0 = (int)floorf(u);
    int y0 = (int)floorf(v);
    x0 = min(max(x0, 0), CUBE_L - 1);
    y0 = min(max(y0, 0), CUBE_L - 1);
    const int x1 = min(x0 + 1, CUBE_L - 1);
    const int y1 = min(y0 + 1, CUBE_L - 1);
    const float wx = u - (float)x0;
    const float wy = v - (float)y0;

    const float w00 = (1.0f - wx) * (1.0f - wy);
    const float w01 = wx * (1.0f - wy);
    const float w10 = (1.0f - wx) * wy;
    const float w11 = wx * wy;

    const int o00 = y0 * CUBE_L + x0;
    const int o01 = y0 * CUBE_L + x1;
    const int o10 = y1 * CUBE_L + x0;
    const int o11 = y1 * CUBE_L + x1;

    // ---- Wait for repack's writes to be visible ----
    cudaGridDependencySynchronize();

    // Issue all 12 gathers up front (MLP).
    uint2 g[N_CH][4];
    #pragma unroll
    for (int c = 0; c < N_CH; c++) {
        const uint2* b = g_xt + (c * 6 + f) * LL;
        g[c][0] = __ldg(b + o00);
        g[c][1] = __ldg(b + o01);
        g[c][2] = __ldg(b + o10);
        g[c][3] = __ldg(b + o11);
    }

    const float w[4] = {w00, w01, w10, w11};

    #pragma unroll
    for (int c = 0; c < N_CH; c++) {
        float r01x = 0.f, r01y = 0.f, r23x = 0.f, r23y = 0.f;
        #pragma unroll
        for (int tap = 0; tap < 4; tap++) {
            float2 a01 = __half22float2(u32_as_h2(g[c][tap].x)); // e0,e1
            float2 a23 = __half22float2(u32_as_h2(g[c][tap].y)); // e2,e3
            r01x += w[tap] * a01.x;
            r01y += w[tap] * a01.y;
            r23x += w[tap] * a23.x;
            r23y += w[tap] * a23.y;
        }
        __stcs(out + (size_t)(0 * N_CH + c) * N_PIX + p, r01x);
        __stcs(out + (size_t)(1 * N_CH + c) * N_PIX + p, r01y);
        __stcs(out + (size_t)(2 * N_CH + c) * N_PIX + p, r23x);
        __stcs(out + (size_t)(3 * N_CH + c) * N_PIX + p, r23y);
    }
}

extern "C" void kernel_launch(void* const* d_in, const int* in_sizes, int n_in,
                              void* d_out, int out_size)
{
    const float*  x    = (const float*)d_in[0];
    const float2* uv   = (const float2*)d_in[1];
    const int*    face = (const int*)d_in[2];
    float*        out  = (float*)d_out;

    // Pass 1: repack — persistent single-wave grid + streaming loads.
    repack_kernel<<<RP_BLOCKS, 256>>>(x);

    // Pass 2: gather — plain max-occupancy grid, PDL-chained.
    cudaLaunchConfig_t cfg = {};
    cfg.gridDim  = dim3(EQU_W / 32, EQU_H / 8);
    cfg.blockDim = dim3(32, 8);
    cfg.dynamicSmemBytes = 0;
    cfg.stream = 0;
    cudaLaunchAttribute attrs[1];
    attrs[0].id = cudaLaunchAttributeProgrammaticStreamSerialization;
    attrs[0].val.programmaticStreamSerializationAllowed = 1;
    cfg.attrs = attrs;
    cfg.numAttrs = 1;
    cudaLaunchKernelEx(&cfg, cube2equirec_kernel, uv, face, out);
}